// round 12
// baseline (speedup 1.0000x reference)
#include <cuda_runtime.h>

// Shapes (fixed for this problem)
#define B_  2
#define T_  2048
#define H_  8
#define D_  64
#define M_  64
#define C_  32                 // chunk length (timesteps per block), both K1 and K2
#define NC_ (T_ / C_)          // 64 chunks per (b,h)
#define RS  512                // row stride in floats between consecutive t (H*D)
#define PAD 68                 // smem row stride in floats (272B, 16B-aligned)
#define PAD4 (PAD / 4)         // 17 float4s per row
#define NSEG 4                 // time segments per chunk (8 steps each)

// Per-(b,h,chunk) column sums of fmap(k): [B*H*NC][D]
__device__ float g_chunksum[B_ * H_ * NC_ * D_];
// Final per-row scale S/den, laid out to match the flat row order of v/out:
// scal[(b*T + t)*H + h]
__device__ float g_scal[B_ * T_ * H_];

__device__ __forceinline__ float fmap(float x) {
    // elu(x) + 1 (alpha=1): x>0 -> x+1 ; x<=0 -> exp(x)
    return x > 0.0f ? x + 1.0f : __expf(x);
}
__device__ __forceinline__ float4 fmap4(float4 a) {
    return make_float4(fmap(a.x), fmap(a.y), fmap(a.z), fmap(a.w));
}
__device__ __forceinline__ float4 add4(float4 a, float4 b) {
    return make_float4(a.x + b.x, a.y + b.y, a.z + b.z, a.w + b.w);
}

// ---------------------------------------------------------------------------
// Kernel 1: per-chunk column sums of fmap(k). grid = 1024 blocks, 256 thr.
// One wave (low regs/smem). Proven ~0.8us.
// ---------------------------------------------------------------------------
__global__ __launch_bounds__(256, 7) void k_chunksum(const float* __restrict__ k) {
    __shared__ float4 red[16][16];          // [tg][dv]
    const int bc  = blockIdx.x;             // bh*64 + c
    const int c   = bc & (NC_ - 1);
    const int bh  = bc >> 6;
    const int h   = bh & (H_ - 1);
    const int b   = bh >> 3;
    const int tid = threadIdx.x;
    const int tg  = tid >> 4;
    const int dv  = tid & 15;

    const size_t base = (((size_t)b * T_ + (size_t)c * C_) * H_ + h) * D_;

    float4 s = make_float4(0.f, 0.f, 0.f, 0.f);
    #pragma unroll
    for (int i = 0; i < 2; i++) {
        const int t = tg + i * 16;
        s = add4(s, fmap4(*(const float4*)(k + base + (size_t)t * RS + dv * 4)));
    }
    red[tg][dv] = s;
    __syncthreads();

    if (tid < 16) {
        float4 acc = red[0][tid];
        #pragma unroll
        for (int t = 1; t < 16; t++) acc = add4(acc, red[t][tid]);
        *(float4*)(&g_chunksum[bc * D_ + tid * 4]) = acc;
    }
}

// ---------------------------------------------------------------------------
// Kernel 2: stats. Reads k,q; emits per-row scale = S/den (incl. carry).
// grid = 1024 blocks, 256 threads, forced 7 blocks/SM -> ONE WAVE.
// ---------------------------------------------------------------------------
__global__ __launch_bounds__(256, 7) void k_stats(const float* __restrict__ k,
                                                  const float* __restrict__ q) {
    __shared__ float loc_s[C_ * PAD];      // fmap(k) -> local inclusive time-scan (in place)
    __shared__ float segsum[NSEG * 64];
    __shared__ float carp[4 * 64];         // carry partials (4-way split over priors)
    __shared__ float carr[64];             // cross-chunk carry per d

    float4* loc4 = (float4*)loc_s;
    float4* ca4  = (float4*)carr;

    const int bc  = blockIdx.x;
    const int c   = bc & (NC_ - 1);
    const int bh  = bc >> 6;
    const int h   = bh & (H_ - 1);
    const int b   = bh >> 3;
    const int tid = threadIdx.x;

    const size_t base = (((size_t)b * T_ + (size_t)c * C_) * H_ + h) * D_;

    // ---- Hoist q LDGs (Phase C operands): in flight through the scan ----
    const int t   = tid >> 3;              // 0..31 (Phase C row)
    const int dgv = tid & 7;               // 0..7  (8 d's per lane)
    const size_t rowg = base + (size_t)t * RS + dgv * 8;
    const float4 qr0 = *(const float4*)(q + rowg);
    const float4 qr1 = *(const float4*)(q + rowg + 4);

    // ---- Carry partials: 4-way chunk split over up to c priors ----
    {
        const int d = tid & 63, p = tid >> 6;
        const int lo = p * 16;
        const int hi = (c < lo + 16) ? c : (lo + 16);
        float run = 0.0f;
        const float* cs = &g_chunksum[(bh << 6) * D_ + d];
        #pragma unroll 4
        for (int cc = lo; cc < hi; cc++) run += cs[cc * D_];
        carp[p * 64 + d] = run;
    }

    // ---- Phase A: coalesced k -> fmap -> smem (STS.128) ----
    #pragma unroll
    for (int it = 0; it < 2; it++) {
        const int i  = tid + it * 256;
        const int tt = i >> 4;
        const int dv = i & 15;
        loc4[tt * PAD4 + dv] = fmap4(*(const float4*)(k + base + (size_t)tt * RS + dv * 4));
    }
    __syncthreads();

    // ---- B1: local inclusive time-scan IN PLACE (64 d x 4 seg, 8 steps) ----
    {
        const int d = tid & 63, seg = tid >> 6;
        float run = 0.0f;
        #pragma unroll
        for (int i = 0; i < C_ / NSEG; i++) {
            const int tt = seg * (C_ / NSEG) + i;
            run += loc_s[tt * PAD + d];
            loc_s[tt * PAD + d] = run;
        }
        segsum[seg * 64 + d] = run;
    }
    __syncthreads();

    // ---- B2 offsets (segs 1..3) || carry reduce (tid<64) ----
    if (tid < 64) {
        carr[tid] = carp[tid] + carp[64 + tid] + carp[128 + tid] + carp[192 + tid];
    } else {
        const int d = tid & 63, seg = tid >> 6;   // 1..3
        float off = segsum[d];
        for (int s = 1; s < seg; s++) off += segsum[s * 64 + d];
        #pragma unroll
        for (int i = 0; i < C_ / NSEG; i++) {
            const int tt = seg * (C_ / NSEG) + i;
            loc_s[tt * PAD + d] += off;
        }
    }
    __syncthreads();

    // ---- Phase C: 8 lanes per timestep; q already in registers ----
    {
        const int b4 = t * PAD4 + dgv * 2;
        float dcum = 0.0f, S = 0.0f, den = 0.0f, qs = 0.0f;
        #pragma unroll
        for (int j = 0; j < 2; j++) {
            const float4 lv = loc4[b4 + j];
            float4 pv = make_float4(0.f, 0.f, 0.f, 0.f);
            if (t > 0) pv = loc4[b4 - PAD4 + j];
            const float4 qf = (j == 0) ? fmap4(qr0) : fmap4(qr1);
            const float4 cv = ca4[dgv * 2 + j];    // warp-uniform -> broadcast

            den += qf.x * (lv.x + cv.x) + qf.y * (lv.y + cv.y)
                 + qf.z * (lv.z + cv.z) + qf.w * (lv.w + cv.w);

            dcum += lv.x - pv.x;  S += qf.x * dcum;
            dcum += lv.y - pv.y;  S += qf.y * dcum;
            dcum += lv.z - pv.z;  S += qf.z * dcum;
            dcum += lv.w - pv.w;  S += qf.w * dcum;
            qs   += qf.x + qf.y + qf.z + qf.w;
        }

        // 8-lane exclusive scan of per-group ktot across dgv
        float incl = dcum;
        #pragma unroll
        for (int o = 1; o < 8; o <<= 1) {
            float n = __shfl_up_sync(0xFFFFFFFFu, incl, o);
            if (dgv >= o) incl += n;
        }
        S += (incl - dcum) * qs;

        // butterfly-reduce S and den within the 8-lane group
        #pragma unroll
        for (int o = 4; o > 0; o >>= 1) {
            S   += __shfl_xor_sync(0xFFFFFFFFu, S, o);
            den += __shfl_xor_sync(0xFFFFFFFFu, den, o);
        }

        if (dgv == 0)
            g_scal[((size_t)b * T_ + c * C_ + t) * H_ + h] = S / den;
    }
}

// ---------------------------------------------------------------------------
// Kernel 3: pure stream: out = v * scal[row]. grid = 1024 blocks, 256 thr,
// 2 float4s per thread (exact cover of 2M floats). ONE WAVE, no barriers.
// ---------------------------------------------------------------------------
__global__ __launch_bounds__(256, 7) void k_scale(const float* __restrict__ v,
                                                  float* __restrict__ out) {
    const int f0 = blockIdx.x * 512 + threadIdx.x;   // float4 index
    const float4* v4 = (const float4*)v;
    float4* o4 = (float4*)out;

    #pragma unroll
    for (int it = 0; it < 2; it++) {
        const int f = f0 + it * 256;
        const float s = g_scal[f >> 4];              // 16 float4s per row -> broadcast
        float4 x = v4[f];
        x.x *= s; x.y *= s; x.z *= s; x.w *= s;
        o4[f] = x;
    }
}

extern "C" void kernel_launch(void* const* d_in, const int* in_sizes, int n_in,
                              void* d_out, int out_size) {
    const float* q = (const float*)d_in[0];
    const float* k = (const float*)d_in[1];
    const float* v = (const float*)d_in[2];
    float* out = (float*)d_out;

    const int nblocks = B_ * H_ * NC_;     // 1024
    k_chunksum<<<nblocks, 256>>>(k);
    k_stats<<<nblocks, 256>>>(k, q);
    k_scale<<<nblocks, 256>>>(v, out);     // 1024 * 512 float4s = 2M floats exactly
}